// round 9
// baseline (speedup 1.0000x reference)
#include <cuda_runtime.h>
#include <cuda_bf16.h>
#include <math.h>
#include <stdint.h>

// ---------------------------------------------------------------- constants
#define NSEQ      400
#define NSEG      50
#define SEGLEN    4
#define C         64
#define TT        200
#define VV        25
#define HID       128
#define GATES     512
#define LEVY      2016
#define LSDIM     2144
#define MROWS     20000
#define MPAD      20096        // 157*128
#define KPAD      2176         // 68*32
#define KSTAGES   68           // K stages of 32 bf16 elems
#define ROWB      (KPAD*2)     // bytes per bf16 row

// ---------------------------------------------------------------- scratch
__device__ __nv_bfloat16 g_Ahi[(size_t)MPAD * KPAD];   // logsig features hi
__device__ __nv_bfloat16 g_Alo[(size_t)MPAD * KPAD];   // logsig features lo
__device__ __nv_bfloat16 g_Bhi[(size_t)GATES * KPAD];  // W_ih hi
__device__ __nv_bfloat16 g_Blo[(size_t)GATES * KPAD];  // W_ih lo
__device__ float g_xproj[(size_t)MROWS * GATES];
__device__ float g_WhhT[HID * GATES];
__device__ float g_bias[GATES];

__device__ __forceinline__ float ex2f(float x) {
    float y; asm("ex2.approx.f32 %0, %1;" : "=f"(y) : "f"(x)); return y;
}
__device__ __forceinline__ float rcpf(float x) {
    float y; asm("rcp.approx.f32 %0, %1;" : "=f"(y) : "f"(x)); return y;
}
__device__ __forceinline__ float fast_sigmoid(float x) {
    return rcpf(1.0f + ex2f(-1.4426950408889634f * x));
}
__device__ __forceinline__ float fast_tanh(float x) {
    return 2.0f * rcpf(1.0f + ex2f(-2.8853900817779268f * x)) - 1.0f;
}

__device__ __forceinline__ uint32_t smem_u32(const void* p) {
    uint32_t a;
    asm("{ .reg .u64 t; cvta.to.shared.u64 t, %1; cvt.u32.u64 %0, t; }" : "=r"(a) : "l"(p));
    return a;
}

static __device__ __forceinline__ void cp16(uint32_t s, const void* g) {
    asm volatile("cp.async.cg.shared.global [%0], [%1], 16;\n" :: "r"(s), "l"(g));
}
#define CP_COMMIT()  asm volatile("cp.async.commit_group;\n" ::: "memory")
#define CP_WAIT0()   asm volatile("cp.async.wait_group 0;\n" ::: "memory")

static __device__ __forceinline__ void ldsm4(uint32_t* r, uint32_t addr) {
    asm volatile("ldmatrix.sync.aligned.m8n8.x4.shared.b16 {%0,%1,%2,%3}, [%4];\n"
                 : "=r"(r[0]), "=r"(r[1]), "=r"(r[2]), "=r"(r[3]) : "r"(addr));
}

static __device__ __forceinline__ void mma16816(float* c, const uint32_t* a,
                                                const uint32_t* b) {
    asm volatile(
        "mma.sync.aligned.m16n8k16.row.col.f32.bf16.bf16.f32 "
        "{%0,%1,%2,%3}, {%4,%5,%6,%7}, {%8,%9}, {%0,%1,%2,%3};\n"
        : "+f"(c[0]), "+f"(c[1]), "+f"(c[2]), "+f"(c[3])
        : "r"(a[0]), "r"(a[1]), "r"(a[2]), "r"(a[3]), "r"(b[0]), "r"(b[1]));
}

// ---------------------------------------------------------------- prep
__global__ void prep_kernel(const float* __restrict__ Whh,
                            const float* __restrict__ bih,
                            const float* __restrict__ bhh) {
    int g = blockIdx.x * blockDim.x + threadIdx.x;
    if (g < GATES) {
        g_bias[g] = bih[g] + bhh[g];
        for (int k = 0; k < HID; k++)
            g_WhhT[k * GATES + g] = Whh[g * HID + k];
    }
}

// convert W_ih row-major f32 -> bf16 hi/lo, K padded to 2176 (pad = 0)
__global__ void wprep_kernel(const float* __restrict__ Wih) {
    int row = blockIdx.x;   // 0..511
    for (int col = threadIdx.x; col < KPAD; col += blockDim.x) {
        float v = (col < LSDIM) ? Wih[(size_t)row * LSDIM + col] : 0.0f;
        __nv_bfloat16 hi = __float2bfloat16_rn(v);
        __nv_bfloat16 lo = __float2bfloat16_rn(v - __bfloat162float(hi));
        g_Bhi[(size_t)row * KPAD + col] = hi;
        g_Blo[(size_t)row * KPAD + col] = lo;
    }
}

// ---------------------------------------------------------------- K1: logsig
#define PSTRIDE 101

__global__ __launch_bounds__(256) void logsig_kernel(const float* __restrict__ x) {
    const int bs = blockIdx.x;           // 0..799
    const int b = bs / NSEG, s = bs % NSEG;
    const int tid = threadIdx.x;

    __shared__ float p[C][PSTRIDE];      // p[c][t*25+v]
    __shared__ uint8_t s_iu[LEVY], s_ju[LEVY];

    for (int idx = tid; idx < C * (SEGLEN * VV); idx += 256) {
        int c = idx / (SEGLEN * VV);
        int r = idx % (SEGLEN * VV);     // r = t*VV + v
        p[c][r] = x[(((size_t)b * C + c) * TT + s * SEGLEN) * VV + r];
    }
    for (int k = tid; k < LEVY; k += 256) {
        int i = 0, rem = k;
        while (rem >= (C - 1 - i)) { rem -= (C - 1 - i); i++; }
        s_iu[k] = (uint8_t)i;
        s_ju[k] = (uint8_t)(i + 1 + rem);
    }
    __syncthreads();

    for (int v = 0; v < VV; v++) {
        const size_t row = ((size_t)(b * VV + v) * NSEG + s);
        __nv_bfloat16* ohi = g_Ahi + row * KPAD;
        __nv_bfloat16* olo = g_Alo + row * KPAD;

        for (int k = tid; k < LSDIM; k += 256) {
            float val;
            if (k < C) {
                val = p[k][3 * VV + v] - p[k][v];
            } else if (k < C + LEVY) {
                int i = s_iu[k - C], j = s_ju[k - C];
                float si = p[i][v], sj = p[j][v];
                float a = 0.0f;
#pragma unroll
                for (int t = 0; t < SEGLEN - 1; t++) {
                    float pit = p[i][t * VV + v], pjt = p[j][t * VV + v];
                    float devi = pit - si;
                    float devj = pjt - sj;
                    float inci = p[i][(t + 1) * VV + v] - pit;
                    float incj = p[j][(t + 1) * VV + v] - pjt;
                    a += devi * incj - devj * inci;
                }
                val = 0.5f * a;
            } else {
                val = p[k - C - LEVY][v];
            }
            __nv_bfloat16 h = __float2bfloat16_rn(val);
            ohi[k] = h;
            olo[k] = __float2bfloat16_rn(val - __bfloat162float(h));
        }
    }
}

// ---------------------------------------------------------------- K2: mma.sync GEMM
// CTA tile M=128 x N=64, BK=32 bf16, 8 warps (warp tile 32x32).
// 2-stage cp.async, 3 CTAs/SM (24 warps) via 85-reg cap + 60KB smem.
// acc += Ahi*Bhi + Ahi*Blo + Alo*Bhi  (f32 accumulate)
#define BKE       32                  // K elems per stage
#define SROW      40                  // smem row stride in bf16 elems (80 B)
#define A_BYTES   (128 * SROW * 2)    // 10240 B per A array
#define B_BYTES   (64  * SROW * 2)    // 5120 B per B array
#define OFF_AHI   0
#define OFF_ALO   (A_BYTES)
#define OFF_BHI   (2 * A_BYTES)
#define OFF_BLO   (2 * A_BYTES + B_BYTES)
#define STG       (2 * A_BYTES + 2 * B_BYTES)   // 30720 B per stage
#define NSTAGE    2
#define GEMM_SMEM (NSTAGE * STG)      // 61440 B

extern __shared__ char dynsm[];

static __device__ __forceinline__ void load_stage(int tid, int bm, int bn, int s,
                                                  uint32_t sbase) {
    size_t kb = (size_t)s * (BKE * 2);   // byte offset into a bf16 row
    // A: 128 rows x 4 chunks(16B) = 512 entries per array, 2 sweeps
#pragma unroll
    for (int i = 0; i < 2; i++) {
        int ch  = tid + i * 256;         // 0..511
        int row = ch >> 2;
        int c   = ch & 3;
        uint32_t dst = (uint32_t)(row * (SROW * 2) + c * 16);
        size_t gA = (size_t)(bm + row) * ROWB + kb + c * 16;
        cp16(sbase + OFF_AHI + dst, (const char*)g_Ahi + gA);
        cp16(sbase + OFF_ALO + dst, (const char*)g_Alo + gA);
    }
    // B: 64 rows x 4 chunks = 256 entries per array, 1 sweep
    {
        int row = tid >> 2;
        int c   = tid & 3;
        uint32_t dst = (uint32_t)(row * (SROW * 2) + c * 16);
        size_t gB = (size_t)(bn + row) * ROWB + kb + c * 16;
        cp16(sbase + OFF_BHI + dst, (const char*)g_Bhi + gB);
        cp16(sbase + OFF_BLO + dst, (const char*)g_Blo + gB);
    }
    CP_COMMIT();
}

__global__ __launch_bounds__(256, 3) void gemm_mma_kernel() {
    __shared__ float s_bias[64];

    const int tid  = threadIdx.x;
    const int bn   = blockIdx.x * 64;    // N fastest: consecutive CTAs share A tile
    const int bm   = blockIdx.y * 128;
    const int lane = tid & 31;
    const int wid  = tid >> 5;
    const int wm   = (wid & 3) * 32;     // warp M origin: 0,32,64,96
    const int wn   = (wid >> 2) * 32;    // warp N origin: 0,32

    const uint32_t sbase = smem_u32(dynsm);

    if (tid < 64) s_bias[tid] = g_bias[bn + tid];

    // ldmatrix per-lane address components
    const int rowA = wm + (lane & 7) + (((lane >> 3) & 1) << 3);
    const int colA = ((lane >> 4) & 1) << 3;
    const int rowB = wn + (lane & 7) + (((lane >> 4) & 1) << 3);
    const int colB = ((lane >> 3) & 1) << 3;

    float acc[2][4][4];
#pragma unroll
    for (int f = 0; f < 2; f++)
#pragma unroll
        for (int n = 0; n < 4; n++)
#pragma unroll
            for (int q = 0; q < 4; q++) acc[f][n][q] = 0.0f;

    // prologue: stage 0
    load_stage(tid, bm, bn, 0, sbase);

    for (int s = 0; s < KSTAGES; s++) {
        CP_WAIT0();          // stage s resident
        __syncthreads();

        if (s + 1 < KSTAGES) // prefetch next stage into the other buffer
            load_stage(tid, bm, bn, s + 1, sbase + (uint32_t)((s + 1) & 1) * STG);

        const uint32_t buf = sbase + (uint32_t)(s & 1) * STG;
#pragma unroll
        for (int kk = 0; kk < BKE; kk += 16) {
            uint32_t bh[2][4], bl[2][4];
#pragma unroll
            for (int p = 0; p < 2; p++) {
                uint32_t off = (uint32_t)(((rowB + 16 * p) * SROW + colB + kk) * 2);
                ldsm4(bh[p], buf + OFF_BHI + off);
                ldsm4(bl[p], buf + OFF_BLO + off);
            }
#pragma unroll
            for (int f = 0; f < 2; f++) {
                uint32_t ah[4], al[4];
                uint32_t off = (uint32_t)(((rowA + 16 * f) * SROW + colA + kk) * 2);
                ldsm4(ah, buf + OFF_AHI + off);
                ldsm4(al, buf + OFF_ALO + off);
#pragma unroll
                for (int n = 0; n < 4; n++) {
                    const uint32_t* Bh = &bh[n >> 1][(n & 1) * 2];
                    const uint32_t* Bl = &bl[n >> 1][(n & 1) * 2];
                    mma16816(acc[f][n], ah, Bh);
                    mma16816(acc[f][n], ah, Bl);
                    mma16816(acc[f][n], al, Bh);
                }
            }
        }
    }

    // epilogue
    const int r0base = bm + wm + (lane >> 2);
    const int cloc   = wn + 2 * (lane & 3);
#pragma unroll
    for (int f = 0; f < 2; f++) {
        int r0 = r0base + f * 16;
        int r1 = r0 + 8;
#pragma unroll
        for (int n = 0; n < 4; n++) {
            int cl = cloc + n * 8;
            if (r0 < MROWS) {
                float2 v;
                v.x = acc[f][n][0] + s_bias[cl];
                v.y = acc[f][n][1] + s_bias[cl + 1];
                *(float2*)&g_xproj[(size_t)r0 * GATES + bn + cl] = v;
            }
            if (r1 < MROWS) {
                float2 v;
                v.x = acc[f][n][2] + s_bias[cl];
                v.y = acc[f][n][3] + s_bias[cl + 1];
                *(float2*)&g_xproj[(size_t)r1 * GATES + bn + cl] = v;
            }
        }
    }
}

// ---------------------------------------------------------------- K3: LSTM
#define REGK 96
#define TAILK 32
#define LSTM_SMEM (TAILK * GATES * 4)

__global__ __launch_bounds__(512, 1) void lstm_kernel(float* __restrict__ out) {
    const int g = threadIdx.x;
    const int n0 = blockIdx.x * 4;

    __shared__ float4 hs[HID];
    __shared__ float  cs[4][HID];
    __shared__ float  gsm[4][GATES];
    float* sWtail = (float*)dynsm;   // [TAILK][GATES]

    float w[REGK];
#pragma unroll
    for (int k = 0; k < REGK; k++) w[k] = g_WhhT[k * GATES + g];
#pragma unroll
    for (int kk = 0; kk < TAILK; kk++)
        sWtail[kk * GATES + g] = g_WhhT[(REGK + kk) * GATES + g];

    if (g < HID) {
        hs[g] = make_float4(0.f, 0.f, 0.f, 0.f);
        cs[0][g] = 0.f; cs[1][g] = 0.f; cs[2][g] = 0.f; cs[3][g] = 0.f;
    }
    __syncthreads();

    const float* xp = g_xproj + (size_t)n0 * NSEG * GATES + g;

    const int m_  = g >> 7;
    const int hid = g & 127;
    const int n   = n0 + m_;
    const int b   = n / VV;
    const int v   = n % VV;
    float* outp = out + ((size_t)(b * HID + hid) * NSEG) * VV + v;

    for (int s = 0; s < NSEG; s++) {
        float a0 = xp[(0 * NSEG + s) * GATES];
        float a1 = xp[(1 * NSEG + s) * GATES];
        float a2 = xp[(2 * NSEG + s) * GATES];
        float a3 = xp[(3 * NSEG + s) * GATES];
#pragma unroll
        for (int k = 0; k < REGK; k++) {
            float4 h4 = hs[k];
            float wk = w[k];
            a0 += h4.x * wk; a1 += h4.y * wk; a2 += h4.z * wk; a3 += h4.w * wk;
        }
#pragma unroll
        for (int kk = 0; kk < TAILK; kk++) {
            float4 h4 = hs[REGK + kk];
            float wk = sWtail[kk * GATES + g];
            a0 += h4.x * wk; a1 += h4.y * wk; a2 += h4.z * wk; a3 += h4.w * wk;
        }
        gsm[0][g] = a0; gsm[1][g] = a1; gsm[2][g] = a2; gsm[3][g] = a3;
        __syncthreads();

        {
            float gi = gsm[m_][hid];
            float gf = gsm[m_][HID + hid];
            float gg = gsm[m_][2 * HID + hid];
            float go = gsm[m_][3 * HID + hid];
            float c  = cs[m_][hid];
            float cn = fast_sigmoid(gf) * c + fast_sigmoid(gi) * fast_tanh(gg);
            float h  = fast_sigmoid(go) * fast_tanh(cn);
            cs[m_][hid] = cn;
            ((float*)&hs[hid])[m_] = h;
            outp[s * VV] = h;
        }
        __syncthreads();
    }
}

// ---------------------------------------------------------------- launch
extern "C" void kernel_launch(void* const* d_in, const int* in_sizes, int n_in,
                              void* d_out, int out_size) {
    const float* x   = (const float*)d_in[0];
    const float* Wih = (const float*)d_in[1];
    const float* Whh = (const float*)d_in[2];
    const float* bih = (const float*)d_in[3];
    const float* bhh = (const float*)d_in[4];
    float* out = (float*)d_out;

    cudaFuncSetAttribute(gemm_mma_kernel,
                         cudaFuncAttributeMaxDynamicSharedMemorySize, GEMM_SMEM);
    cudaFuncSetAttribute(lstm_kernel,
                         cudaFuncAttributeMaxDynamicSharedMemorySize, LSTM_SMEM);

    prep_kernel<<<2, 256>>>(Whh, bih, bhh);
    wprep_kernel<<<GATES, 256>>>(Wih);
    logsig_kernel<<<16 * NSEG, 256>>>(x);
    dim3 grid(GATES / 64, MPAD / 128);   // (8, 157), N fastest
    gemm_mma_kernel<<<grid, 256, GEMM_SMEM>>>();
    lstm_kernel<<<NSEQ / 4, 512, LSTM_SMEM>>>(out);
}